// round 5
// baseline (speedup 1.0000x reference)
#include <cuda_runtime.h>
#include <math.h>
#include <stdint.h>

// ---------------------------------------------------------------------------
// Problem constants
// ---------------------------------------------------------------------------
#define BATCH   2
#define SEQ     4096
#define DMODEL  1024
#define DINNER  2048
#define NHEADS  16
#define HDIM    128
#define DSTATE  16
#define DCONV   4
#define CHUNK   64
#define NCHUNK  (SEQ / CHUNK)      // 64
#define M_ROWS  (BATCH * SEQ)      // 8192
#define NPROJ   (NHEADS + 2*DSTATE) // 48
#define LN_EPS  1e-5f

// ---------------------------------------------------------------------------
// Scratch (static device globals -- no allocation allowed)
// ---------------------------------------------------------------------------
__device__ float g_xz[(size_t)M_ROWS * 2 * DINNER];     // [xe | z]
__device__ float g_xc[(size_t)M_ROWS * DINNER];
__device__ float g_proj[(size_t)M_ROWS * NPROJ];        // dt_raw | B | C
__device__ float g_y[(size_t)M_ROWS * DINNER];
__device__ float g_S[(size_t)BATCH*NHEADS*NCHUNK*HDIM*DSTATE];
__device__ float g_P[(size_t)BATCH*NHEADS*NCHUNK*HDIM];

// ---------------------------------------------------------------------------
// Helpers (IEEE-accurate transcendentals; tf32 GEMMs own the error budget)
// ---------------------------------------------------------------------------
__device__ __forceinline__ uint32_t tf32_rn(float x) {
    uint32_t r;
    asm("cvt.rna.tf32.f32 %0, %1;" : "=r"(r) : "f"(x));
    return r;
}
__device__ __forceinline__ uint4 cvt4(float4 v) {
    uint4 u;
    u.x = tf32_rn(v.x); u.y = tf32_rn(v.y); u.z = tf32_rn(v.z); u.w = tf32_rn(v.w);
    return u;
}
__device__ __forceinline__ void mma_tf32(float* c, const uint32_t* a, const uint32_t* b) {
    asm volatile(
        "mma.sync.aligned.m16n8k8.row.col.f32.tf32.tf32.f32 "
        "{%0,%1,%2,%3},{%4,%5,%6,%7},{%8,%9},{%0,%1,%2,%3};"
        : "+f"(c[0]), "+f"(c[1]), "+f"(c[2]), "+f"(c[3])
        : "r"(a[0]), "r"(a[1]), "r"(a[2]), "r"(a[3]), "r"(b[0]), "r"(b[1]));
}
__device__ __forceinline__ float softplus_acc(float x) {
    return (x > 20.f) ? x : log1pf(expf(x));
}
__device__ __forceinline__ float silu_acc(float v) {
    return v / (1.f + expf(-v));
}

// ---------------------------------------------------------------------------
// TF32 tensor-core GEMM: C[M,N] = A[M,K] @ B[K,N], row-major fp32 in/out.
// M,N %128==0, K %16==0. 128 threads, BM=BN=128, BK=16, warp tile 64x64.
// ---------------------------------------------------------------------------
__global__ __launch_bounds__(128, 2) void gemm_tf32(
    const float* __restrict__ A, const float* __restrict__ B,
    float* __restrict__ C, int M, int N, int K)
{
    __shared__ uint32_t As[2][128][20];   // [buf][m][k], padded
    __shared__ uint32_t Bs[2][16][136];   // [buf][k][n], padded

    const int tid  = threadIdx.x;
    const int warp = tid >> 5, lane = tid & 31;
    const int g    = lane >> 2, q = lane & 3;
    const int wm   = (warp & 1) * 64;
    const int wn   = (warp >> 1) * 64;
    const int m0   = blockIdx.y * 128;
    const int n0   = blockIdx.x * 128;

    const int ar = tid;                 // A row 0..127 (stages full 16-k row)
    const int br = tid & 15;            // B row 0..15
    const int bc = (tid >> 4) * 16;     // B col segment

    const float* Aptr = A + (size_t)(m0 + ar) * K;
    const float* Bptr = B + (size_t)br * N + n0 + bc;

    float acc[4][8][4];
#pragma unroll
    for (int i = 0; i < 4; i++)
#pragma unroll
        for (int j = 0; j < 8; j++)
#pragma unroll
            for (int k = 0; k < 4; k++) acc[i][j][k] = 0.f;

    {
#pragma unroll
        for (int c = 0; c < 4; c++) {
            float4 av = *(const float4*)(Aptr + c * 4);
            float4 bv = *(const float4*)(Bptr + c * 4);
            *(uint4*)&As[0][ar][c * 4]      = cvt4(av);
            *(uint4*)&Bs[0][br][bc + c * 4] = cvt4(bv);
        }
    }
    __syncthreads();

    const int nk = K >> 4;
    for (int kt = 0; kt < nk; kt++) {
        const int cur = kt & 1;

        float4 na[4], nb[4];
        if (kt + 1 < nk) {
            const float* Ap = Aptr + (kt + 1) * 16;
            const float* Bp = Bptr + (size_t)(kt + 1) * 16 * N;
#pragma unroll
            for (int c = 0; c < 4; c++) {
                na[c] = *(const float4*)(Ap + c * 4);
                nb[c] = *(const float4*)(Bp + c * 4);
            }
        }

#pragma unroll
        for (int ks = 0; ks < 2; ks++) {
            const int kk = ks * 8 + q;
            uint32_t af[4][4], bf[8][2];
#pragma unroll
            for (int tm = 0; tm < 4; tm++) {
                const int r = wm + tm * 16 + g;
                af[tm][0] = As[cur][r][kk];
                af[tm][1] = As[cur][r + 8][kk];
                af[tm][2] = As[cur][r][kk + 4];
                af[tm][3] = As[cur][r + 8][kk + 4];
            }
#pragma unroll
            for (int tn = 0; tn < 8; tn++) {
                const int n = wn + tn * 8 + g;
                bf[tn][0] = Bs[cur][kk][n];
                bf[tn][1] = Bs[cur][kk + 4][n];
            }
#pragma unroll
            for (int tm = 0; tm < 4; tm++)
#pragma unroll
                for (int tn = 0; tn < 8; tn++)
                    mma_tf32(acc[tm][tn], af[tm], bf[tn]);
        }

        if (kt + 1 < nk) {
            const int nxt = cur ^ 1;
#pragma unroll
            for (int c = 0; c < 4; c++) {
                *(uint4*)&As[nxt][ar][c * 4]      = cvt4(na[c]);
                *(uint4*)&Bs[nxt][br][bc + c * 4] = cvt4(nb[c]);
            }
        }
        __syncthreads();
    }

#pragma unroll
    for (int tm = 0; tm < 4; tm++) {
        const int row = m0 + wm + tm * 16 + g;
#pragma unroll
        for (int tn = 0; tn < 8; tn++) {
            const int col = n0 + wn + tn * 8 + 2 * q;
            *(float2*)&C[(size_t)row * N + col] =
                make_float2(acc[tm][tn][0], acc[tm][tn][1]);
            *(float2*)&C[(size_t)(row + 8) * N + col] =
                make_float2(acc[tm][tn][2], acc[tm][tn][3]);
        }
    }
}

// ---------------------------------------------------------------------------
// Depthwise causal conv (taps=4) + bias + silu.
// ---------------------------------------------------------------------------
__global__ __launch_bounds__(256) void conv_silu_kernel(
    const float* __restrict__ conv_w, const float* __restrict__ conv_b)
{
    int idx = blockIdx.x * 256 + threadIdx.x;
    int c4  = idx & (DINNER / 4 - 1);
    int m   = idx >> 9;
    int c   = c4 << 2;
    int t   = m & (SEQ - 1);

    float w[4][4];
#pragma unroll
    for (int cc = 0; cc < 4; cc++) {
        float4 wv = *(const float4*)(conv_w + (size_t)(c + cc) * 4);
        w[cc][0] = wv.x; w[cc][1] = wv.y; w[cc][2] = wv.z; w[cc][3] = wv.w;
    }
    float4 bv  = *(const float4*)(conv_b + c);
    float acc[4] = {bv.x, bv.y, bv.z, bv.w};

#pragma unroll
    for (int j = 0; j < 4; j++) {
        int tj = t - 3 + j;
        if (tj >= 0) {
            float4 xv = *(const float4*)(g_xz + (size_t)(m - 3 + j) * (2 * DINNER) + c);
            acc[0] = fmaf(w[0][j], xv.x, acc[0]);
            acc[1] = fmaf(w[1][j], xv.y, acc[1]);
            acc[2] = fmaf(w[2][j], xv.z, acc[2]);
            acc[3] = fmaf(w[3][j], xv.w, acc[3]);
        }
    }
    float4 o;
    o.x = silu_acc(acc[0]);
    o.y = silu_acc(acc[1]);
    o.z = silu_acc(acc[2]);
    o.w = silu_acc(acc[3]);
    *(float4*)(g_xc + (size_t)m * DINNER + c) = o;
}

// ---------------------------------------------------------------------------
// proj[M,48] = xc[M,2048] @ W_xproj[2048,48].
// ---------------------------------------------------------------------------
__global__ __launch_bounds__(256) void proj_kernel(const float* __restrict__ W_xproj)
{
    __shared__ float xs[32][128];
    __shared__ float ws[128][NPROJ];
    const int tid = threadIdx.x;
    const int m0  = blockIdx.x * 32;

    float acc[6];
#pragma unroll
    for (int o = 0; o < 6; o++) acc[o] = 0.f;

    for (int k0 = 0; k0 < DINNER; k0 += 128) {
        for (int t = tid; t < 1024; t += 256) {
            int r  = t >> 5;
            int kk = (t & 31) << 2;
            *(float4*)&xs[r][kk] = *(const float4*)(g_xc + (size_t)(m0 + r) * DINNER + k0 + kk);
        }
        for (int t = tid; t < 128 * NPROJ; t += 256) {
            int kk = t / NPROJ;
            int j  = t - kk * NPROJ;
            ws[kk][j] = W_xproj[(size_t)(k0 + kk) * NPROJ + j];
        }
        __syncthreads();
#pragma unroll
        for (int o = 0; o < 6; o++) {
            int oi = o * 256 + tid;
            int r  = oi / NPROJ;
            int j  = oi - r * NPROJ;
            float a = acc[o];
#pragma unroll 8
            for (int kk = 0; kk < 128; kk++)
                a = fmaf(xs[r][kk], ws[kk][j], a);
            acc[o] = a;
        }
        __syncthreads();
    }
#pragma unroll
    for (int o = 0; o < 6; o++) {
        int oi = o * 256 + tid;
        int r  = oi / NPROJ;
        int j  = oi - r * NPROJ;
        g_proj[(size_t)(m0 + r) * NPROJ + j] = acc[o];
    }
}

// ---------------------------------------------------------------------------
// Chunked scan, pass 1 (dt + decay recomputed on the fly).
// NOTE: g_P must be the PRODUCT of all 64 per-step decays exp(Ah*cum_t),
// NOT exp(Ah*cum_final) -- that bug cost rounds 3 and 4.
// ---------------------------------------------------------------------------
__global__ __launch_bounds__(128) void scan_pass1(
    const float* __restrict__ W_dt, const float* __restrict__ b_dt,
    const float* __restrict__ A_log)
{
    const int blk = blockIdx.x;
    const int c   = blk & (NCHUNK - 1);
    const int h   = (blk >> 6) & (NHEADS - 1);
    const int b   = blk >> 10;
    const int d   = threadIdx.x;
    const int i   = h * HDIM + d;

    __shared__ float sB[CHUNK][DSTATE];
    __shared__ float sR[CHUNK][NHEADS];
    for (int t = threadIdx.x; t < CHUNK * DSTATE; t += 128) {
        int tt = t >> 4, n = t & 15;
        size_t pm = (size_t)(b * SEQ + c * CHUNK + tt) * NPROJ;
        sB[tt][n] = g_proj[pm + NHEADS + n];
        sR[tt][n] = g_proj[pm + n];
    }
    __syncthreads();

    float w[NHEADS];
#pragma unroll
    for (int hh = 0; hh < NHEADS; hh++) w[hh] = W_dt[(size_t)hh * DINNER + i];
    const float bd = b_dt[i];
    const float Ah = -expf(A_log[h]);

    float s[DSTATE];
#pragma unroll
    for (int n = 0; n < DSTATE; n++) s[n] = 0.f;
    float cum = 0.f;
    float P   = 1.f;

    const int mbase = b * SEQ + c * CHUNK;
    for (int tt = 0; tt < CHUNK; tt++) {
        float raw = bd;
#pragma unroll
        for (int hh = 0; hh < NHEADS; hh++) raw = fmaf(sR[tt][hh], w[hh], raw);
        float dtv = softplus_acc(raw);
        cum += dtv;
        float a = expf(Ah * cum);
        P *= a;                                  // product of per-step decays
        float u = dtv * g_xc[(size_t)(mbase + tt) * DINNER + i];
#pragma unroll
        for (int n = 0; n < DSTATE; n++)
            s[n] = fmaf(s[n], a, u * sB[tt][n]);
    }
    const int base = ((b * NHEADS + h) * NCHUNK + c) * HDIM + d;
    g_P[base] = P;
#pragma unroll
    for (int n = 0; n < DSTATE; n++) g_S[(size_t)base * DSTATE + n] = s[n];
}

// ---------------------------------------------------------------------------
// Pass 2: stitch across chunks
// ---------------------------------------------------------------------------
__global__ __launch_bounds__(128) void scan_pass2()
{
    int idx = blockIdx.x * 128 + threadIdx.x;
    int d   = idx & (HDIM - 1);
    int bh  = idx >> 7;

    float s[DSTATE];
#pragma unroll
    for (int n = 0; n < DSTATE; n++) s[n] = 0.f;

    for (int c = 0; c < NCHUNK; c++) {
        int base = (bh * NCHUNK + c) * HDIM + d;
        float Pv = g_P[base];
#pragma unroll
        for (int n = 0; n < DSTATE; n++) {
            float Sl = g_S[(size_t)base * DSTATE + n];
            g_S[(size_t)base * DSTATE + n] = s[n];
            s[n] = fmaf(Pv, s[n], Sl);
        }
    }
}

// ---------------------------------------------------------------------------
// Pass 3: replay + y = C.s + D*x, gate with silu(z)
// ---------------------------------------------------------------------------
__global__ __launch_bounds__(128) void scan_pass3(
    const float* __restrict__ W_dt, const float* __restrict__ b_dt,
    const float* __restrict__ A_log, const float* __restrict__ D_skip)
{
    const int blk = blockIdx.x;
    const int c   = blk & (NCHUNK - 1);
    const int h   = (blk >> 6) & (NHEADS - 1);
    const int b   = blk >> 10;
    const int d   = threadIdx.x;
    const int i   = h * HDIM + d;

    __shared__ float sB[CHUNK][DSTATE];
    __shared__ float sC[CHUNK][DSTATE];
    __shared__ float sR[CHUNK][NHEADS];
    for (int t = threadIdx.x; t < CHUNK * DSTATE; t += 128) {
        int tt = t >> 4, n = t & 15;
        size_t pm = (size_t)(b * SEQ + c * CHUNK + tt) * NPROJ;
        sB[tt][n] = g_proj[pm + NHEADS + n];
        sC[tt][n] = g_proj[pm + NHEADS + DSTATE + n];
        sR[tt][n] = g_proj[pm + n];
    }
    __syncthreads();

    float w[NHEADS];
#pragma unroll
    for (int hh = 0; hh < NHEADS; hh++) w[hh] = W_dt[(size_t)hh * DINNER + i];
    const float bd = b_dt[i];
    const float Ah = -expf(A_log[h]);
    const float Dh = D_skip[h];

    const int base = ((b * NHEADS + h) * NCHUNK + c) * HDIM + d;
    float s[DSTATE];
#pragma unroll
    for (int n = 0; n < DSTATE; n++) s[n] = g_S[(size_t)base * DSTATE + n];

    float cum = 0.f;
    const int mbase = b * SEQ + c * CHUNK;
    for (int tt = 0; tt < CHUNK; tt++) {
        float raw = bd;
#pragma unroll
        for (int hh = 0; hh < NHEADS; hh++) raw = fmaf(sR[tt][hh], w[hh], raw);
        float dtv = softplus_acc(raw);
        cum += dtv;
        float a = expf(Ah * cum);
        size_t off = (size_t)(mbase + tt) * DINNER + i;
        float x = g_xc[off];
        float u = dtv * x;
        float y = 0.f;
#pragma unroll
        for (int n = 0; n < DSTATE; n++) {
            s[n] = fmaf(s[n], a, u * sB[tt][n]);
            y    = fmaf(s[n], sC[tt][n], y);
        }
        y = fmaf(Dh, x, y);
        float zv = g_xz[(size_t)(mbase + tt) * (2 * DINNER) + DINNER + i];
        y *= silu_acc(zv);
        g_y[off] = y;
    }
}

// ---------------------------------------------------------------------------
// LayerNorm in place on g_y.
// ---------------------------------------------------------------------------
__global__ __launch_bounds__(256) void layernorm_kernel(
    const float* __restrict__ ln_g, const float* __restrict__ ln_b)
{
    __shared__ float sh[8];
    __shared__ float s_mu, s_rstd;
    const int m   = blockIdx.x;
    const int tid = threadIdx.x;
    float* row = g_y + (size_t)m * DINNER;

    const int i0 = tid * 4;
    float4 a  = *(float4*)(row + i0);
    float4 b4 = *(float4*)(row + 1024 + i0);
    float v[8] = {a.x, a.y, a.z, a.w, b4.x, b4.y, b4.z, b4.w};

    float sum = 0.f;
#pragma unroll
    for (int k = 0; k < 8; k++) sum += v[k];
#pragma unroll
    for (int o = 16; o > 0; o >>= 1) sum += __shfl_xor_sync(0xffffffffu, sum, o);
    if ((tid & 31) == 0) sh[tid >> 5] = sum;
    __syncthreads();
    if (tid < 32) {
        float t = (tid < 8) ? sh[tid] : 0.f;
#pragma unroll
        for (int o = 4; o > 0; o >>= 1) t += __shfl_xor_sync(0xffffffffu, t, o);
        if (tid == 0) s_mu = t * (1.f / (float)DINNER);
    }
    __syncthreads();
    const float mu = s_mu;

    float var = 0.f;
#pragma unroll
    for (int k = 0; k < 8; k++) { float dv = v[k] - mu; var = fmaf(dv, dv, var); }
#pragma unroll
    for (int o = 16; o > 0; o >>= 1) var += __shfl_xor_sync(0xffffffffu, var, o);
    __syncthreads();
    if ((tid & 31) == 0) sh[tid >> 5] = var;
    __syncthreads();
    if (tid < 32) {
        float t = (tid < 8) ? sh[tid] : 0.f;
#pragma unroll
        for (int o = 4; o > 0; o >>= 1) t += __shfl_xor_sync(0xffffffffu, t, o);
        if (tid == 0) s_rstd = rsqrtf(t * (1.f / (float)DINNER) + LN_EPS);
    }
    __syncthreads();
    const float rstd = s_rstd;

    float4 o1, o2;
    o1.x = (v[0] - mu) * rstd * ln_g[i0 + 0] + ln_b[i0 + 0];
    o1.y = (v[1] - mu) * rstd * ln_g[i0 + 1] + ln_b[i0 + 1];
    o1.z = (v[2] - mu) * rstd * ln_g[i0 + 2] + ln_b[i0 + 2];
    o1.w = (v[3] - mu) * rstd * ln_g[i0 + 3] + ln_b[i0 + 3];
    o2.x = (v[4] - mu) * rstd * ln_g[1024 + i0 + 0] + ln_b[1024 + i0 + 0];
    o2.y = (v[5] - mu) * rstd * ln_g[1024 + i0 + 1] + ln_b[1024 + i0 + 1];
    o2.z = (v[6] - mu) * rstd * ln_g[1024 + i0 + 2] + ln_b[1024 + i0 + 2];
    o2.w = (v[7] - mu) * rstd * ln_g[1024 + i0 + 3] + ln_b[1024 + i0 + 3];
    *(float4*)(row + i0)        = o1;
    *(float4*)(row + 1024 + i0) = o2;
}

// ---------------------------------------------------------------------------
// kernel_launch
// ---------------------------------------------------------------------------
extern "C" void kernel_launch(void* const* d_in, const int* in_sizes, int n_in,
                              void* d_out, int out_size)
{
    const float* x       = (const float*)d_in[0];
    const float* W_in    = (const float*)d_in[1];
    const float* conv_w  = (const float*)d_in[2];
    const float* conv_b  = (const float*)d_in[3];
    const float* W_xproj = (const float*)d_in[4];
    const float* W_dt    = (const float*)d_in[5];
    const float* b_dt    = (const float*)d_in[6];
    const float* A_log   = (const float*)d_in[7];
    const float* D_skip  = (const float*)d_in[8];
    const float* W_out   = (const float*)d_in[9];
    const float* ln_g    = (const float*)d_in[10];
    const float* ln_b    = (const float*)d_in[11];
    float* out = (float*)d_out;

    float *pxz = nullptr, *py = nullptr;
    cudaGetSymbolAddress((void**)&pxz, g_xz);
    cudaGetSymbolAddress((void**)&py,  g_y);

    // 1) xz = x @ W_in   [8192,1024]x[1024,4096]  (tf32 TC, 64x64 warp tile)
    dim3 g1(2 * DINNER / 128, M_ROWS / 128);
    gemm_tf32<<<g1, 128>>>(x, W_in, pxz, M_ROWS, 2 * DINNER, DMODEL);

    // 2) depthwise conv + silu -> g_xc
    conv_silu_kernel<<<(M_ROWS * DINNER / 4) / 256, 256>>>(conv_w, conv_b);

    // 3) proj = xc @ W_xproj -> g_proj
    proj_kernel<<<M_ROWS / 32, 256>>>(W_xproj);

    // 4) chunked scan (dt/decay fused into passes 1 & 3)
    scan_pass1<<<BATCH * NHEADS * NCHUNK, 128>>>(W_dt, b_dt, A_log);
    scan_pass2<<<(BATCH * NHEADS * HDIM) / 128, 128>>>();
    scan_pass3<<<BATCH * NHEADS * NCHUNK, 128>>>(W_dt, b_dt, A_log, D_skip);

    // 5) layernorm in place on g_y
    layernorm_kernel<<<M_ROWS, 256>>>(ln_g, ln_b);

    // 6) out = y_ln @ W_out   [8192,2048]x[2048,1024]
    dim3 g2(DMODEL / 128, M_ROWS / 128);
    gemm_tf32<<<g2, 128>>>(py, W_out, out, M_ROWS, DMODEL, DINNER);
}

// round 6
// speedup vs baseline: 1.2274x; 1.2274x over previous
#include <cuda_runtime.h>
#include <math.h>
#include <stdint.h>

// ---------------------------------------------------------------------------
// Problem constants
// ---------------------------------------------------------------------------
#define BATCH   2
#define SEQ     4096
#define DMODEL  1024
#define DINNER  2048
#define NHEADS  16
#define HDIM    128
#define DSTATE  16
#define DCONV   4
#define CHUNK   64
#define NCHUNK  (SEQ / CHUNK)      // 64
#define M_ROWS  (BATCH * SEQ)      // 8192
#define NPROJ   (NHEADS + 2*DSTATE) // 48
#define LN_EPS  1e-5f

// ---------------------------------------------------------------------------
// Scratch (static device globals -- no allocation allowed)
// ---------------------------------------------------------------------------
__device__ float g_xz[(size_t)M_ROWS * 2 * DINNER];     // [xe | z]
__device__ float g_xc[(size_t)M_ROWS * DINNER];
__device__ float g_proj[(size_t)M_ROWS * NPROJ];        // dt_raw | B | C
__device__ float g_y[(size_t)M_ROWS * DINNER];
__device__ float g_S[(size_t)BATCH*NHEADS*NCHUNK*HDIM*DSTATE];
__device__ float g_P[(size_t)BATCH*NHEADS*NCHUNK*HDIM];

// ---------------------------------------------------------------------------
// Helpers (IEEE-accurate transcendentals; tf32 GEMMs own the error budget)
// ---------------------------------------------------------------------------
__device__ __forceinline__ uint32_t tf32_rn(float x) {
    uint32_t r;
    asm("cvt.rna.tf32.f32 %0, %1;" : "=r"(r) : "f"(x));
    return r;
}
__device__ __forceinline__ uint4 cvt4(float4 v) {
    uint4 u;
    u.x = tf32_rn(v.x); u.y = tf32_rn(v.y); u.z = tf32_rn(v.z); u.w = tf32_rn(v.w);
    return u;
}
__device__ __forceinline__ void mma_tf32(float* c, const uint32_t* a, const uint32_t* b) {
    asm volatile(
        "mma.sync.aligned.m16n8k8.row.col.f32.tf32.tf32.f32 "
        "{%0,%1,%2,%3},{%4,%5,%6,%7},{%8,%9},{%0,%1,%2,%3};"
        : "+f"(c[0]), "+f"(c[1]), "+f"(c[2]), "+f"(c[3])
        : "r"(a[0]), "r"(a[1]), "r"(a[2]), "r"(a[3]), "r"(b[0]), "r"(b[1]));
}
__device__ __forceinline__ float softplus_acc(float x) {
    return (x > 20.f) ? x : log1pf(expf(x));
}
__device__ __forceinline__ float silu_acc(float v) {
    return v / (1.f + expf(-v));
}

// ---------------------------------------------------------------------------
// TF32 tensor-core GEMM (R2 configuration -- measured good):
// C[M,N] = A[M,K] @ B[K,N], row-major fp32 in/out.
// 256 threads, BM=BN=128, BK=16, warp tile 64x32, double-buffered smem.
// ---------------------------------------------------------------------------
__global__ __launch_bounds__(256, 2) void gemm_tf32(
    const float* __restrict__ A, const float* __restrict__ B,
    float* __restrict__ C, int M, int N, int K)
{
    __shared__ uint32_t As[2][128][20];   // [buf][m][k], padded
    __shared__ uint32_t Bs[2][16][136];   // [buf][k][n], padded

    const int tid  = threadIdx.x;
    const int warp = tid >> 5, lane = tid & 31;
    const int g    = lane >> 2, q = lane & 3;
    const int wm   = (warp & 1) * 64;
    const int wn   = (warp >> 1) * 32;
    const int m0   = blockIdx.y * 128;
    const int n0   = blockIdx.x * 128;

    // staging assignments
    const int ar = tid >> 1;            // A row 0..127
    const int ac = (tid & 1) * 8;       // A col 0 or 8
    const int br = tid >> 4;            // B row 0..15
    const int bc = (tid & 15) * 8;      // B col 0..120

    const float* Aptr = A + (size_t)(m0 + ar) * K + ac;
    const float* Bptr = B + (size_t)br * N + n0 + bc;

    float acc[4][4][4];
#pragma unroll
    for (int i = 0; i < 4; i++)
#pragma unroll
        for (int j = 0; j < 4; j++)
#pragma unroll
            for (int k = 0; k < 4; k++) acc[i][j][k] = 0.f;

    // preload tile 0
    {
        float4 a0 = *(const float4*)(Aptr);
        float4 a1 = *(const float4*)(Aptr + 4);
        float4 b0 = *(const float4*)(Bptr);
        float4 b1 = *(const float4*)(Bptr + 4);
        *(uint4*)&As[0][ar][ac]     = cvt4(a0);
        *(uint4*)&As[0][ar][ac + 4] = cvt4(a1);
        *(uint4*)&Bs[0][br][bc]     = cvt4(b0);
        *(uint4*)&Bs[0][br][bc + 4] = cvt4(b1);
    }
    __syncthreads();

    const int nk = K >> 4;
    for (int kt = 0; kt < nk; kt++) {
        const int cur = kt & 1;

        float4 na0, na1, nb0, nb1;
        if (kt + 1 < nk) {
            const float* Ap = Aptr + (kt + 1) * 16;
            const float* Bp = Bptr + (size_t)(kt + 1) * 16 * N;
            na0 = *(const float4*)(Ap);
            na1 = *(const float4*)(Ap + 4);
            nb0 = *(const float4*)(Bp);
            nb1 = *(const float4*)(Bp + 4);
        }

#pragma unroll
        for (int ks = 0; ks < 2; ks++) {
            uint32_t af[4][4], bf[4][2];
            const int kk = ks * 8 + q;
#pragma unroll
            for (int tm = 0; tm < 4; tm++) {
                const int r = wm + tm * 16 + g;
                af[tm][0] = As[cur][r][kk];
                af[tm][1] = As[cur][r + 8][kk];
                af[tm][2] = As[cur][r][kk + 4];
                af[tm][3] = As[cur][r + 8][kk + 4];
            }
#pragma unroll
            for (int tn = 0; tn < 4; tn++) {
                const int n = wn + tn * 8 + g;
                bf[tn][0] = Bs[cur][kk][n];
                bf[tn][1] = Bs[cur][kk + 4][n];
            }
#pragma unroll
            for (int tm = 0; tm < 4; tm++)
#pragma unroll
                for (int tn = 0; tn < 4; tn++)
                    mma_tf32(acc[tm][tn], af[tm], bf[tn]);
        }

        if (kt + 1 < nk) {
            const int nxt = cur ^ 1;
            *(uint4*)&As[nxt][ar][ac]     = cvt4(na0);
            *(uint4*)&As[nxt][ar][ac + 4] = cvt4(na1);
            *(uint4*)&Bs[nxt][br][bc]     = cvt4(nb0);
            *(uint4*)&Bs[nxt][br][bc + 4] = cvt4(nb1);
        }
        __syncthreads();
    }

#pragma unroll
    for (int tm = 0; tm < 4; tm++) {
        const int row = m0 + wm + tm * 16 + g;
#pragma unroll
        for (int tn = 0; tn < 4; tn++) {
            const int col = n0 + wn + tn * 8 + 2 * q;
            *(float2*)&C[(size_t)row * N + col] =
                make_float2(acc[tm][tn][0], acc[tm][tn][1]);
            *(float2*)&C[(size_t)(row + 8) * N + col] =
                make_float2(acc[tm][tn][2], acc[tm][tn][3]);
        }
    }
}

// ---------------------------------------------------------------------------
// Depthwise causal conv (taps=4) + bias + silu.
// ---------------------------------------------------------------------------
__global__ __launch_bounds__(256) void conv_silu_kernel(
    const float* __restrict__ conv_w, const float* __restrict__ conv_b)
{
    int idx = blockIdx.x * 256 + threadIdx.x;
    int c4  = idx & (DINNER / 4 - 1);
    int m   = idx >> 9;
    int c   = c4 << 2;
    int t   = m & (SEQ - 1);

    float w[4][4];
#pragma unroll
    for (int cc = 0; cc < 4; cc++) {
        float4 wv = *(const float4*)(conv_w + (size_t)(c + cc) * 4);
        w[cc][0] = wv.x; w[cc][1] = wv.y; w[cc][2] = wv.z; w[cc][3] = wv.w;
    }
    float4 bv  = *(const float4*)(conv_b + c);
    float acc[4] = {bv.x, bv.y, bv.z, bv.w};

#pragma unroll
    for (int j = 0; j < 4; j++) {
        int tj = t - 3 + j;
        if (tj >= 0) {
            float4 xv = *(const float4*)(g_xz + (size_t)(m - 3 + j) * (2 * DINNER) + c);
            acc[0] = fmaf(w[0][j], xv.x, acc[0]);
            acc[1] = fmaf(w[1][j], xv.y, acc[1]);
            acc[2] = fmaf(w[2][j], xv.z, acc[2]);
            acc[3] = fmaf(w[3][j], xv.w, acc[3]);
        }
    }
    float4 o;
    o.x = silu_acc(acc[0]);
    o.y = silu_acc(acc[1]);
    o.z = silu_acc(acc[2]);
    o.w = silu_acc(acc[3]);
    *(float4*)(g_xc + (size_t)m * DINNER + c) = o;
}

// ---------------------------------------------------------------------------
// proj[M,48] = xc[M,2048] @ W_xproj[2048,48].
// ---------------------------------------------------------------------------
__global__ __launch_bounds__(256) void proj_kernel(const float* __restrict__ W_xproj)
{
    __shared__ float xs[32][128];
    __shared__ float ws[128][NPROJ];
    const int tid = threadIdx.x;
    const int m0  = blockIdx.x * 32;

    float acc[6];
#pragma unroll
    for (int o = 0; o < 6; o++) acc[o] = 0.f;

    for (int k0 = 0; k0 < DINNER; k0 += 128) {
        for (int t = tid; t < 1024; t += 256) {
            int r  = t >> 5;
            int kk = (t & 31) << 2;
            *(float4*)&xs[r][kk] = *(const float4*)(g_xc + (size_t)(m0 + r) * DINNER + k0 + kk);
        }
        for (int t = tid; t < 128 * NPROJ; t += 256) {
            int kk = t / NPROJ;
            int j  = t - kk * NPROJ;
            ws[kk][j] = W_xproj[(size_t)(k0 + kk) * NPROJ + j];
        }
        __syncthreads();
#pragma unroll
        for (int o = 0; o < 6; o++) {
            int oi = o * 256 + tid;
            int r  = oi / NPROJ;
            int j  = oi - r * NPROJ;
            float a = acc[o];
#pragma unroll 8
            for (int kk = 0; kk < 128; kk++)
                a = fmaf(xs[r][kk], ws[kk][j], a);
            acc[o] = a;
        }
        __syncthreads();
    }
#pragma unroll
    for (int o = 0; o < 6; o++) {
        int oi = o * 256 + tid;
        int r  = oi / NPROJ;
        int j  = oi - r * NPROJ;
        g_proj[(size_t)(m0 + r) * NPROJ + j] = acc[o];
    }
}

// ---------------------------------------------------------------------------
// Chunked scan, pass 1 (dt + decay recomputed on the fly).
// g_P is the PRODUCT of all 64 per-step decays (NOT exp(Ah*cum_final)).
// ---------------------------------------------------------------------------
__global__ __launch_bounds__(128) void scan_pass1(
    const float* __restrict__ W_dt, const float* __restrict__ b_dt,
    const float* __restrict__ A_log)
{
    const int blk = blockIdx.x;
    const int c   = blk & (NCHUNK - 1);
    const int h   = (blk >> 6) & (NHEADS - 1);
    const int b   = blk >> 10;
    const int d   = threadIdx.x;
    const int i   = h * HDIM + d;

    __shared__ float sB[CHUNK][DSTATE];
    __shared__ float sR[CHUNK][NHEADS];
    for (int t = threadIdx.x; t < CHUNK * DSTATE; t += 128) {
        int tt = t >> 4, n = t & 15;
        size_t pm = (size_t)(b * SEQ + c * CHUNK + tt) * NPROJ;
        sB[tt][n] = g_proj[pm + NHEADS + n];
        sR[tt][n] = g_proj[pm + n];
    }
    __syncthreads();

    float w[NHEADS];
#pragma unroll
    for (int hh = 0; hh < NHEADS; hh++) w[hh] = W_dt[(size_t)hh * DINNER + i];
    const float bd = b_dt[i];
    const float Ah = -expf(A_log[h]);

    float s[DSTATE];
#pragma unroll
    for (int n = 0; n < DSTATE; n++) s[n] = 0.f;
    float cum = 0.f;
    float P   = 1.f;

    const int mbase = b * SEQ + c * CHUNK;
    for (int tt = 0; tt < CHUNK; tt++) {
        float raw = bd;
#pragma unroll
        for (int hh = 0; hh < NHEADS; hh++) raw = fmaf(sR[tt][hh], w[hh], raw);
        float dtv = softplus_acc(raw);
        cum += dtv;
        float a = expf(Ah * cum);
        P *= a;                                  // product of per-step decays
        float u = dtv * g_xc[(size_t)(mbase + tt) * DINNER + i];
#pragma unroll
        for (int n = 0; n < DSTATE; n++)
            s[n] = fmaf(s[n], a, u * sB[tt][n]);
    }
    const int base = ((b * NHEADS + h) * NCHUNK + c) * HDIM + d;
    g_P[base] = P;
#pragma unroll
    for (int n = 0; n < DSTATE; n++) g_S[(size_t)base * DSTATE + n] = s[n];
}

// ---------------------------------------------------------------------------
// Pass 2: stitch across chunks
// ---------------------------------------------------------------------------
__global__ __launch_bounds__(128) void scan_pass2()
{
    int idx = blockIdx.x * 128 + threadIdx.x;
    int d   = idx & (HDIM - 1);
    int bh  = idx >> 7;

    float s[DSTATE];
#pragma unroll
    for (int n = 0; n < DSTATE; n++) s[n] = 0.f;

    for (int c = 0; c < NCHUNK; c++) {
        int base = (bh * NCHUNK + c) * HDIM + d;
        float Pv = g_P[base];
#pragma unroll
        for (int n = 0; n < DSTATE; n++) {
            float Sl = g_S[(size_t)base * DSTATE + n];
            g_S[(size_t)base * DSTATE + n] = s[n];
            s[n] = fmaf(Pv, s[n], Sl);
        }
    }
}

// ---------------------------------------------------------------------------
// Pass 3: replay + y = C.s + D*x, gate with silu(z)
// ---------------------------------------------------------------------------
__global__ __launch_bounds__(128) void scan_pass3(
    const float* __restrict__ W_dt, const float* __restrict__ b_dt,
    const float* __restrict__ A_log, const float* __restrict__ D_skip)
{
    const int blk = blockIdx.x;
    const int c   = blk & (NCHUNK - 1);
    const int h   = (blk >> 6) & (NHEADS - 1);
    const int b   = blk >> 10;
    const int d   = threadIdx.x;
    const int i   = h * HDIM + d;

    __shared__ float sB[CHUNK][DSTATE];
    __shared__ float sC[CHUNK][DSTATE];
    __shared__ float sR[CHUNK][NHEADS];
    for (int t = threadIdx.x; t < CHUNK * DSTATE; t += 128) {
        int tt = t >> 4, n = t & 15;
        size_t pm = (size_t)(b * SEQ + c * CHUNK + tt) * NPROJ;
        sB[tt][n] = g_proj[pm + NHEADS + n];
        sC[tt][n] = g_proj[pm + NHEADS + DSTATE + n];
        sR[tt][n] = g_proj[pm + n];
    }
    __syncthreads();

    float w[NHEADS];
#pragma unroll
    for (int hh = 0; hh < NHEADS; hh++) w[hh] = W_dt[(size_t)hh * DINNER + i];
    const float bd = b_dt[i];
    const float Ah = -expf(A_log[h]);
    const float Dh = D_skip[h];

    const int base = ((b * NHEADS + h) * NCHUNK + c) * HDIM + d;
    float s[DSTATE];
#pragma unroll
    for (int n = 0; n < DSTATE; n++) s[n] = g_S[(size_t)base * DSTATE + n];

    float cum = 0.f;
    const int mbase = b * SEQ + c * CHUNK;
    for (int tt = 0; tt < CHUNK; tt++) {
        float raw = bd;
#pragma unroll
        for (int hh = 0; hh < NHEADS; hh++) raw = fmaf(sR[tt][hh], w[hh], raw);
        float dtv = softplus_acc(raw);
        cum += dtv;
        float a = expf(Ah * cum);
        size_t off = (size_t)(mbase + tt) * DINNER + i;
        float x = g_xc[off];
        float u = dtv * x;
        float y = 0.f;
#pragma unroll
        for (int n = 0; n < DSTATE; n++) {
            s[n] = fmaf(s[n], a, u * sB[tt][n]);
            y    = fmaf(s[n], sC[tt][n], y);
        }
        y = fmaf(Dh, x, y);
        float zv = g_xz[(size_t)(mbase + tt) * (2 * DINNER) + DINNER + i];
        y *= silu_acc(zv);
        g_y[off] = y;
    }
}

// ---------------------------------------------------------------------------
// LayerNorm in place on g_y.
// ---------------------------------------------------------------------------
__global__ __launch_bounds__(256) void layernorm_kernel(
    const float* __restrict__ ln_g, const float* __restrict__ ln_b)
{
    __shared__ float sh[8];
    __shared__ float s_mu, s_rstd;
    const int m   = blockIdx.x;
    const int tid = threadIdx.x;
    float* row = g_y + (size_t)m * DINNER;

    const int i0 = tid * 4;
    float4 a  = *(float4*)(row + i0);
    float4 b4 = *(float4*)(row + 1024 + i0);
    float v[8] = {a.x, a.y, a.z, a.w, b4.x, b4.y, b4.z, b4.w};

    float sum = 0.f;
#pragma unroll
    for (int k = 0; k < 8; k++) sum += v[k];
#pragma unroll
    for (int o = 16; o > 0; o >>= 1) sum += __shfl_xor_sync(0xffffffffu, sum, o);
    if ((tid & 31) == 0) sh[tid >> 5] = sum;
    __syncthreads();
    if (tid < 32) {
        float t = (tid < 8) ? sh[tid] : 0.f;
#pragma unroll
        for (int o = 4; o > 0; o >>= 1) t += __shfl_xor_sync(0xffffffffu, t, o);
        if (tid == 0) s_mu = t * (1.f / (float)DINNER);
    }
    __syncthreads();
    const float mu = s_mu;

    float var = 0.f;
#pragma unroll
    for (int k = 0; k < 8; k++) { float dv = v[k] - mu; var = fmaf(dv, dv, var); }
#pragma unroll
    for (int o = 16; o > 0; o >>= 1) var += __shfl_xor_sync(0xffffffffu, var, o);
    __syncthreads();
    if ((tid & 31) == 0) sh[tid >> 5] = var;
    __syncthreads();
    if (tid < 32) {
        float t = (tid < 8) ? sh[tid] : 0.f;
#pragma unroll
        for (int o = 4; o > 0; o >>= 1) t += __shfl_xor_sync(0xffffffffu, t, o);
        if (tid == 0) s_rstd = rsqrtf(t * (1.f / (float)DINNER) + LN_EPS);
    }
    __syncthreads();
    const float rstd = s_rstd;

    float4 o1, o2;
    o1.x = (v[0] - mu) * rstd * ln_g[i0 + 0] + ln_b[i0 + 0];
    o1.y = (v[1] - mu) * rstd * ln_g[i0 + 1] + ln_b[i0 + 1];
    o1.z = (v[2] - mu) * rstd * ln_g[i0 + 2] + ln_b[i0 + 2];
    o1.w = (v[3] - mu) * rstd * ln_g[i0 + 3] + ln_b[i0 + 3];
    o2.x = (v[4] - mu) * rstd * ln_g[1024 + i0 + 0] + ln_b[1024 + i0 + 0];
    o2.y = (v[5] - mu) * rstd * ln_g[1024 + i0 + 1] + ln_b[1024 + i0 + 1];
    o2.z = (v[6] - mu) * rstd * ln_g[1024 + i0 + 2] + ln_b[1024 + i0 + 2];
    o2.w = (v[7] - mu) * rstd * ln_g[1024 + i0 + 3] + ln_b[1024 + i0 + 3];
    *(float4*)(row + i0)        = o1;
    *(float4*)(row + 1024 + i0) = o2;
}

// ---------------------------------------------------------------------------
// kernel_launch
// ---------------------------------------------------------------------------
extern "C" void kernel_launch(void* const* d_in, const int* in_sizes, int n_in,
                              void* d_out, int out_size)
{
    const float* x       = (const float*)d_in[0];
    const float* W_in    = (const float*)d_in[1];
    const float* conv_w  = (const float*)d_in[2];
    const float* conv_b  = (const float*)d_in[3];
    const float* W_xproj = (const float*)d_in[4];
    const float* W_dt    = (const float*)d_in[5];
    const float* b_dt    = (const float*)d_in[6];
    const float* A_log   = (const float*)d_in[7];
    const float* D_skip  = (const float*)d_in[8];
    const float* W_out   = (const float*)d_in[9];
    const float* ln_g    = (const float*)d_in[10];
    const float* ln_b    = (const float*)d_in[11];
    float* out = (float*)d_out;

    float *pxz = nullptr, *py = nullptr;
    cudaGetSymbolAddress((void**)&pxz, g_xz);
    cudaGetSymbolAddress((void**)&py,  g_y);

    // 1) xz = x @ W_in   [8192,1024]x[1024,4096]  (tf32 TC, 256-thr config)
    dim3 g1(2 * DINNER / 128, M_ROWS / 128);
    gemm_tf32<<<g1, 256>>>(x, W_in, pxz, M_ROWS, 2 * DINNER, DMODEL);

    // 2) depthwise conv + silu -> g_xc
    conv_silu_kernel<<<(M_ROWS * DINNER / 4) / 256, 256>>>(conv_w, conv_b);

    // 3) proj = xc @ W_xproj -> g_proj
    proj_kernel<<<M_ROWS / 32, 256>>>(W_xproj);

    // 4) chunked scan (dt/decay fused into passes 1 & 3)
    scan_pass1<<<BATCH * NHEADS * NCHUNK, 128>>>(W_dt, b_dt, A_log);
    scan_pass2<<<(BATCH * NHEADS * HDIM) / 128, 128>>>();
    scan_pass3<<<BATCH * NHEADS * NCHUNK, 128>>>(W_dt, b_dt, A_log, D_skip);

    // 5) layernorm in place on g_y
    layernorm_kernel<<<M_ROWS, 256>>>(ln_g, ln_b);

    // 6) out = y_ln @ W_out   [8192,2048]x[2048,1024]
    dim3 g2(DMODEL / 128, M_ROWS / 128);
    gemm_tf32<<<g2, 256>>>(py, W_out, out, M_ROWS, DMODEL, DINNER);
}